// round 6
// baseline (speedup 1.0000x reference)
#include <cuda_runtime.h>

#define BATCH 2048
#define CELL 512
#define KDIM 30
#define LPAD 1024
#define VDIM 80

// scratch: [B, 90] = alpha | beta | kappa (kappa pre-summed with kappa_old)
__device__ float g_params[BATCH * 3 * KDIM];

// ---------------------------------------------------------------------------
// Kernel A: params = exp(x @ W.T + b).  8 batches per block (grid=256).
// Thread-per-(batch,output) full dot products: no shuffles, no reduction.
// x tile in smem (broadcast reads); W via float4 gmem loads (L1-resident).
// ---------------------------------------------------------------------------
__global__ __launch_bounds__(256) void params_kernel(
    const float* __restrict__ x,          // [B, CELL]
    const float* __restrict__ kappa_old,  // [B, K]
    const float* __restrict__ W,          // [3K, CELL]
    const float* __restrict__ bias,       // [3K]
    float* __restrict__ out_kappa)        // [B, K]
{
    __shared__ float4 xs[8 * CELL / 4];   // 16 KB

    const int tid = threadIdx.x;
    const int b0 = blockIdx.x * 8;

    const float4* xg = (const float4*)(x + (size_t)b0 * CELL);
    #pragma unroll
    for (int i = tid; i < 8 * CELL / 4; i += 256)
        xs[i] = xg[i];
    __syncthreads();

    // 720 items = 8 batches x 90 outputs; <=3 per thread
    for (int item = tid; item < 8 * 3 * KDIM; item += 256) {
        const int b_loc = item / (3 * KDIM);
        const int o     = item - b_loc * (3 * KDIM);
        const int b     = b0 + b_loc;

        const float4* wrow = (const float4*)(W + (size_t)o * CELL);
        const float4* xr   = xs + b_loc * (CELL / 4);
        float acc = 0.0f;
        #pragma unroll 4
        for (int j = 0; j < CELL / 4; j++) {
            float4 w4 = wrow[j];
            float4 x4 = xr[j];
            acc = fmaf(w4.x, x4.x,
                  fmaf(w4.y, x4.y,
                  fmaf(w4.z, x4.z,
                  fmaf(w4.w, x4.w, acc))));
        }
        float p = __expf(acc + bias[o]);
        if (o >= 2 * KDIM) {
            int k = o - 2 * KDIM;
            p += kappa_old[(size_t)b * KDIM + k];
            out_kappa[(size_t)b * KDIM + k] = p;
        }
        g_params[(size_t)b * (3 * KDIM) + o] = p;
    }
}

// ---------------------------------------------------------------------------
// Kernel B: sparse phi.  One block per batch; each Gaussian only touched
// where beta*(kappa-l)^2 < 92 (beyond that expf underflows -> 0, matching
// the fp32 reference within tolerance).
// ---------------------------------------------------------------------------
__global__ __launch_bounds__(256) void phi_kernel(
    const float* __restrict__ text_lens,  // [B, 1]
    float* __restrict__ out_phi)          // [B, L+1]
{
    __shared__ float s_par[3 * KDIM];
    __shared__ float s_phi[LPAD + 1];

    const int bid = blockIdx.x;
    const int tid = threadIdx.x;
    const int wid = tid >> 5;
    const int lane = tid & 31;

    if (tid < 3 * KDIM)
        s_par[tid] = g_params[(size_t)bid * (3 * KDIM) + tid];
    #pragma unroll
    for (int l = tid; l <= LPAD; l += 256)
        s_phi[l] = 0.0f;
    __syncthreads();

    for (int k = wid; k < KDIM; k += 8) {
        const float alpha = s_par[k];
        const float beta  = s_par[KDIM + k];
        const float kap   = s_par[2 * KDIM + k];
        const float r = fminf(sqrtf(92.0f / beta), 1100.0f);
        const int lo = max(0, (int)(kap - r));
        const int hi = min(LPAD, (int)(kap + r) + 1);
        for (int l = lo + lane; l <= hi; l += 32) {
            float d = kap - (float)l;
            atomicAdd(&s_phi[l], alpha * __expf(-beta * d * d));
        }
    }
    __syncthreads();

    const float scale = (float)LPAD / text_lens[bid];
    for (int l = tid; l <= LPAD; l += 256)
        out_phi[(size_t)bid * (LPAD + 1) + l] = s_phi[l] * scale;
}

// ---------------------------------------------------------------------------
// Kernel C: persistent streaming w reduction.  grid = 148*5, grid-stride over
// batches.  No min-blocks clause (round-5 lesson: forcing 6 caused spills).
// ---------------------------------------------------------------------------
__global__ __launch_bounds__(256) void wsum_kernel(
    const float4* __restrict__ onehots,   // [B, L*V/4]
    const float* __restrict__ phi,        // [B, L+1]
    float* __restrict__ out_w)            // [B, V]
{
    __shared__ float s_phi[LPAD];
    __shared__ float s_w[VDIM];

    const int tid = threadIdx.x;

    // per-thread invariant geometry: float4 index tid + 256j; column base
    // has period 5 in j, row l advances +64 per 5-group.
    int l0[5], cb[5];
    #pragma unroll
    for (int m = 0; m < 5; m++) {
        int e0 = 4 * tid + 1024 * m;
        l0[m] = e0 / VDIM;
        cb[m] = e0 % VDIM;
    }

    for (int bid = blockIdx.x; bid < BATCH; bid += gridDim.x) {
        #pragma unroll
        for (int i = tid; i < LPAD; i += 256)
            s_phi[i] = phi[(size_t)bid * (LPAD + 1) + i];
        if (tid < VDIM) s_w[tid] = 0.0f;
        __syncthreads();

        const float4* oh = onehots + (size_t)bid * (LPAD * VDIM / 4);

        float4 acc[5];
        #pragma unroll
        for (int m = 0; m < 5; m++)
            acc[m] = make_float4(0.f, 0.f, 0.f, 0.f);

        #pragma unroll 2
        for (int g = 0; g < 16; g++) {
            #pragma unroll
            for (int m = 0; m < 5; m++) {
                float4 v4 = __ldcs(&oh[tid + 256 * (m + 5 * g)]);
                float ph = s_phi[l0[m] + 64 * g];
                acc[m].x = fmaf(ph, v4.x, acc[m].x);
                acc[m].y = fmaf(ph, v4.y, acc[m].y);
                acc[m].z = fmaf(ph, v4.z, acc[m].z);
                acc[m].w = fmaf(ph, v4.w, acc[m].w);
            }
        }
        __syncthreads();

        #pragma unroll
        for (int m = 0; m < 5; m++) {
            atomicAdd(&s_w[cb[m] + 0], acc[m].x);
            atomicAdd(&s_w[cb[m] + 1], acc[m].y);
            atomicAdd(&s_w[cb[m] + 2], acc[m].z);
            atomicAdd(&s_w[cb[m] + 3], acc[m].w);
        }
        __syncthreads();

        if (tid < VDIM) out_w[(size_t)bid * VDIM + tid] = s_w[tid];
        __syncthreads();
    }
}

extern "C" void kernel_launch(void* const* d_in, const int* in_sizes, int n_in,
                              void* d_out, int out_size) {
    const float* x         = (const float*)d_in[0];
    const float* kappa_old = (const float*)d_in[1];
    const float4* onehots  = (const float4*)d_in[2];
    const float* text_lens = (const float*)d_in[3];
    const float* W         = (const float*)d_in[4];
    const float* bias      = (const float*)d_in[5];

    float* out = (float*)d_out;
    float* out_w     = out;                                  // [B, V]
    float* out_kappa = out + (size_t)BATCH * VDIM;           // [B, K]
    float* out_phi   = out + (size_t)BATCH * (VDIM + KDIM);  // [B, L+1]

    params_kernel<<<BATCH / 8, 256>>>(x, kappa_old, W, bias, out_kappa);
    phi_kernel<<<BATCH, 256>>>(text_lens, out_phi);
    wsum_kernel<<<148 * 5, 256>>>(onehots, out_phi, out_w);
}

// round 7
// speedup vs baseline: 1.7408x; 1.7408x over previous
#include <cuda_runtime.h>

#define BATCH 2048
#define CELL 512
#define KDIM 30
#define LPAD 1024
#define VDIM 80

// scratch: [B, 90] = alpha | beta | kappa (kappa pre-summed with kappa_old)
__device__ float g_params[BATCH * 3 * KDIM];

// ---------------------------------------------------------------------------
// Kernel A: params = exp(x @ W.T + b).  8 batches/block, 512 threads, grid 256.
// Warp-per-output: lanes stride CELL (coalesced W float4 loads, conflict-free
// padded smem x), 8 batch-accumulators share every W load, butterfly reduce.
// ---------------------------------------------------------------------------
__global__ __launch_bounds__(512) void params_kernel(
    const float* __restrict__ x,          // [B, CELL]
    const float* __restrict__ kappa_old,  // [B, K]
    const float* __restrict__ W,          // [3K, CELL]
    const float* __restrict__ bias,       // [3K]
    float* __restrict__ out_kappa)        // [B, K]
{
    __shared__ float4 xs[8][CELL / 4 + 1];   // pad to keep rows bank-shifted

    const int tid = threadIdx.x;
    const int wid = tid >> 5;               // 16 warps
    const int lane = tid & 31;
    const int b0 = blockIdx.x * 8;

    const float4* xg = (const float4*)(x + (size_t)b0 * CELL);
    for (int i = tid; i < 8 * CELL / 4; i += 512) {
        int r = i >> 7;                      // /128
        int j = i & 127;
        xs[r][j] = xg[r * 128 + j];
    }
    __syncthreads();

    // 90 outputs round-robin over 16 warps
    for (int o = wid; o < 3 * KDIM; o += 16) {
        const float4* wrow = (const float4*)(W + (size_t)o * CELL);
        float a[8];
        #pragma unroll
        for (int r = 0; r < 8; r++) a[r] = 0.0f;

        #pragma unroll
        for (int j4 = 0; j4 < 4; j4++) {
            float4 w4 = wrow[lane + 32 * j4];
            #pragma unroll
            for (int r = 0; r < 8; r++) {
                float4 v = xs[r][lane + 32 * j4];
                a[r] = fmaf(w4.x, v.x,
                       fmaf(w4.y, v.y,
                       fmaf(w4.z, v.z,
                       fmaf(w4.w, v.w, a[r]))));
            }
        }
        #pragma unroll
        for (int off = 16; off; off >>= 1) {
            #pragma unroll
            for (int r = 0; r < 8; r++)
                a[r] += __shfl_xor_sync(0xffffffffu, a[r], off);
        }
        if (lane < 8) {
            int b = b0 + lane;
            float p = __expf(a[lane] + bias[o]);
            if (o >= 2 * KDIM) {
                int k = o - 2 * KDIM;
                p += kappa_old[(size_t)b * KDIM + k];
                out_kappa[(size_t)b * KDIM + k] = p;
            }
            g_params[(size_t)b * (3 * KDIM) + o] = p;
        }
    }
}

// ---------------------------------------------------------------------------
// Kernel B: sparse phi.  One block per batch; Gaussian k only touched where
// beta*(kappa-l)^2 < 92 (beyond that expf underflows -> 0 as in fp32 ref).
// ---------------------------------------------------------------------------
__global__ __launch_bounds__(256) void phi_kernel(
    const float* __restrict__ text_lens,  // [B, 1]
    float* __restrict__ out_phi)          // [B, L+1]
{
    __shared__ float s_par[3 * KDIM];
    __shared__ float s_phi[LPAD + 1];

    const int bid = blockIdx.x;
    const int tid = threadIdx.x;
    const int wid = tid >> 5;
    const int lane = tid & 31;

    if (tid < 3 * KDIM)
        s_par[tid] = g_params[(size_t)bid * (3 * KDIM) + tid];
    #pragma unroll
    for (int l = tid; l <= LPAD; l += 256)
        s_phi[l] = 0.0f;
    __syncthreads();

    for (int k = wid; k < KDIM; k += 8) {
        const float alpha = s_par[k];
        const float beta  = s_par[KDIM + k];
        const float kap   = s_par[2 * KDIM + k];
        const float r = fminf(sqrtf(92.0f / beta), 1100.0f);
        const int lo = max(0, (int)(kap - r));
        const int hi = min(LPAD, (int)(kap + r) + 1);
        for (int l = lo + lane; l <= hi; l += 32) {
            float d = kap - (float)l;
            atomicAdd(&s_phi[l], alpha * __expf(-beta * d * d));
        }
    }
    __syncthreads();

    const float scale = (float)LPAD / text_lens[bid];
    for (int l = tid; l <= LPAD; l += 256)
        out_phi[(size_t)bid * (LPAD + 1) + l] = s_phi[l] * scale;
}

// ---------------------------------------------------------------------------
// Kernel C: streaming w reduction — EXACT round-2 measured-best config
// (grid 2048, block 256, 117.4us @ 73.4% DRAM).
// ---------------------------------------------------------------------------
__global__ __launch_bounds__(256) void wsum_kernel(
    const float4* __restrict__ onehots,   // [B, L*V/4]
    const float* __restrict__ phi,        // [B, L+1]
    float* __restrict__ out_w)            // [B, V]
{
    __shared__ float s_phi[LPAD];
    __shared__ float s_w[VDIM];

    const int bid = blockIdx.x;
    const int tid = threadIdx.x;

    #pragma unroll
    for (int i = tid; i < LPAD; i += 256)
        s_phi[i] = phi[(size_t)bid * (LPAD + 1) + i];
    if (tid < VDIM) s_w[tid] = 0.0f;
    __syncthreads();

    const float4* oh = onehots + (size_t)bid * (LPAD * VDIM / 4);

    float4 acc[5];
    int l0[5], cb[5];
    #pragma unroll
    for (int m = 0; m < 5; m++) {
        int e0 = 4 * tid + 1024 * m;
        l0[m] = e0 / VDIM;
        cb[m] = e0 % VDIM;
        acc[m] = make_float4(0.f, 0.f, 0.f, 0.f);
    }

    #pragma unroll 2
    for (int g = 0; g < 16; g++) {
        #pragma unroll
        for (int m = 0; m < 5; m++) {
            float4 v4 = __ldcs(&oh[tid + 256 * (m + 5 * g)]);
            float ph = s_phi[l0[m] + 64 * g];
            acc[m].x = fmaf(ph, v4.x, acc[m].x);
            acc[m].y = fmaf(ph, v4.y, acc[m].y);
            acc[m].z = fmaf(ph, v4.z, acc[m].z);
            acc[m].w = fmaf(ph, v4.w, acc[m].w);
        }
    }
    __syncthreads();

    #pragma unroll
    for (int m = 0; m < 5; m++) {
        atomicAdd(&s_w[cb[m] + 0], acc[m].x);
        atomicAdd(&s_w[cb[m] + 1], acc[m].y);
        atomicAdd(&s_w[cb[m] + 2], acc[m].z);
        atomicAdd(&s_w[cb[m] + 3], acc[m].w);
    }
    __syncthreads();

    if (tid < VDIM) out_w[(size_t)bid * VDIM + tid] = s_w[tid];
}

extern "C" void kernel_launch(void* const* d_in, const int* in_sizes, int n_in,
                              void* d_out, int out_size) {
    const float* x         = (const float*)d_in[0];
    const float* kappa_old = (const float*)d_in[1];
    const float4* onehots  = (const float4*)d_in[2];
    const float* text_lens = (const float*)d_in[3];
    const float* W         = (const float*)d_in[4];
    const float* bias      = (const float*)d_in[5];

    float* out = (float*)d_out;
    float* out_w     = out;                                  // [B, V]
    float* out_kappa = out + (size_t)BATCH * VDIM;           // [B, K]
    float* out_phi   = out + (size_t)BATCH * (VDIM + KDIM);  // [B, L+1]

    params_kernel<<<BATCH / 8, 512>>>(x, kappa_old, W, bias, out_kappa);
    phi_kernel<<<BATCH, 256>>>(text_lens, out_phi);
    wsum_kernel<<<BATCH, 256>>>(onehots, out_phi, out_w);
}